// round 5
// baseline (speedup 1.0000x reference)
#include <cuda_runtime.h>
#include <cuda_bf16.h>
#include <cuda_fp16.h>
#include <cstdint>

// ---------------- problem constants ----------------
#define BB   2
#define SS   1024
#define BS   2048          // B*S
#define DIM  4096
#define HH   32
#define QL   1536
#define KVL  512
#define NOPE 128
#define ROPE 64
#define VD   128
#define QKH  192           // NOPE+ROPE
#define CAT  576           // KVL+ROPE
#define QD   6144          // H*QKH
#define CAT2 288           // CAT/2
#define QD2  3072

#define NEGV   (-1e9f)
#define SCALEV 0.07216878364870322f   // 192^-0.5
#define EPSV   1e-6f

// ---------------- scratch (device globals; no allocation allowed) ----------
// fp32 intermediates
__device__ float g_qlora_f[(long long)BS * QL];
__device__ float g_kv_f   [(long long)BS * CAT];
__device__ float g_kvcat_f[(long long)BS * CAT];
__device__ float g_scores [64LL * 1024 * 1024];
// split planes (u32 = packed half2 k-pair), hi / lo
__device__ uint32_t g_xh[(long long)BS*2048],      g_xl[(long long)BS*2048];
__device__ uint32_t g_wqaT_h[1536LL*2048],         g_wqaT_l[1536LL*2048];
__device__ uint32_t g_wkvaT_h[576LL*2048],         g_wkvaT_l[576LL*2048];
__device__ uint32_t g_wqbT_h[6144LL*768],          g_wqbT_l[6144LL*768];
__device__ uint32_t g_wkvb1T_h[32LL*512*64],       g_wkvb1T_l[32LL*512*64];
__device__ uint32_t g_wkvb2_h[32LL*128*256],       g_wkvb2_l[32LL*128*256];
__device__ uint32_t g_woT_h[4096LL*2048],          g_woT_l[4096LL*2048];
__device__ uint32_t g_ql_h[(long long)BS*768],     g_ql_l[(long long)BS*768];
__device__ uint32_t g_kvc_h[(long long)BS*CAT2],   g_kvc_l[(long long)BS*CAT2];
__device__ uint32_t g_kvT_h[2LL*512*512],          g_kvT_l[2LL*512*512];
__device__ uint32_t g_q_h[(long long)BS*QD2],      g_q_l[(long long)BS*QD2];
__device__ uint32_t g_qcat_h[(long long)BS*HH*CAT2], g_qcat_l[(long long)BS*HH*CAT2];
__device__ uint32_t g_P_h[64LL*1024*512],          g_P_l[64LL*1024*512];
__device__ uint32_t g_attn_h[(long long)BS*HH*256], g_attn_l[(long long)BS*HH*256];
__device__ uint32_t g_proj_h[(long long)BS*2048],  g_proj_l[(long long)BS*2048];

// ---------------- helpers ----------------
__device__ __forceinline__ void split2(float x, float y, uint32_t& hi, uint32_t& lo) {
    __half hx = __float2half_rn(x), hy = __float2half_rn(y);
    float rx = x - __half2float(hx);
    float ry = y - __half2float(hy);
    __half2 h = __halves2half2(hx, hy);
    __half2 l = __floats2half2_rn(rx, ry);
    hi = *reinterpret_cast<uint32_t*>(&h);
    lo = *reinterpret_cast<uint32_t*>(&l);
}
__device__ __forceinline__ void unsplit(uint32_t hi, uint32_t lo, float& x, float& y) {
    __half2 h = *reinterpret_cast<__half2*>(&hi);
    __half2 l = *reinterpret_cast<__half2*>(&lo);
    x = __half2float(__low2half(h))  + __half2float(__low2half(l));
    y = __half2float(__high2half(h)) + __half2float(__high2half(l));
}
__device__ __forceinline__ void mma16(float c[4], const uint32_t a[4], const uint32_t b[2]) {
    asm volatile(
        "mma.sync.aligned.m16n8k16.row.col.f32.f16.f16.f32 "
        "{%0,%1,%2,%3},{%4,%5,%6,%7},{%8,%9},{%0,%1,%2,%3};\n"
        : "+f"(c[0]), "+f"(c[1]), "+f"(c[2]), "+f"(c[3])
        : "r"(a[0]), "r"(a[1]), "r"(a[2]), "r"(a[3]), "r"(b[0]), "r"(b[1]));
}
__device__ __forceinline__ void cp16(uint32_t saddr, const void* g, bool valid) {
    int sz = valid ? 16 : 0;
    asm volatile("cp.async.ca.shared.global [%0], [%1], 16, %2;\n"
                 :: "r"(saddr), "l"(g), "r"(sz));
}
__device__ __forceinline__ void cp_commit() {
    asm volatile("cp.async.commit_group;\n");
}
template<int NN>
__device__ __forceinline__ void cp_wait() {
    asm volatile("cp.async.wait_group %0;\n" :: "n"(NN));
}

// ---------------- planes GEMM ----------------
// C[m,n] = sum_k A[m,k]*B[n,k]  (both operands pre-split fp16 hi/lo planes,
// [row][k2] u32 layout).  OUT: 0=f32 store, 1=scores epilogue (f32, scale+mask,
// masked-tile fast path), 2=split-plane store.  CK: causal K bound.
// CTA 128x128, BK=16 (8 pairs), 8 warps 2x4, warp tile 64x32; 2-stage cp.async.
#define PK 12
template<int OUT, bool CK>
__global__ __launch_bounds__(256, 2)
void gemm2(const uint32_t* __restrict__ Ah, const uint32_t* __restrict__ Al,
           const uint32_t* __restrict__ Bh, const uint32_t* __restrict__ Bl,
           float* __restrict__ Cf, uint32_t* __restrict__ Ch, uint32_t* __restrict__ Cl,
           int M, int N, int K2,
           int lda2, int ldb2, int ldc,
           long long bA1, long long bA2,
           long long bB1, long long bB2,
           long long bC1, long long bC2, int nz2)
{
    const int z  = blockIdx.z;
    const int z1 = z / nz2;
    const int z2 = z - z1 * nz2;
    const long long aoff = z1 * bA1 + z2 * bA2;
    const long long boff = z1 * bB1 + z2 * bB2;
    const long long coff = z1 * bC1 + z2 * bC2;
    Ah += aoff; Al += aoff; Bh += boff; Bl += boff;

    const int m0  = blockIdx.y * 128;
    const int n0  = blockIdx.x * 128;
    const int tid = threadIdx.x;

    if (OUT == 1 && n0 >= m0 + 128) {
        float* Cz = Cf + coff;
        for (int e = tid; e < 128 * 128; e += 256) {
            int r = e >> 7, c = e & 127;
            Cz[(long long)(m0 + r) * ldc + n0 + c] = NEGV;
        }
        return;
    }

    __shared__ uint32_t sA[2][2][128 * PK];   // [stage][hi/lo]
    __shared__ uint32_t sB[2][2][128 * PK];

    const uint32_t sA0 = (uint32_t)__cvta_generic_to_shared(&sA[0][0][0]);
    const uint32_t sB0 = (uint32_t)__cvta_generic_to_shared(&sB[0][0][0]);

    const int crow = tid >> 1;            // 0..127
    const int cq   = (tid & 1) << 2;      // 0 or 4 u32
    const bool bval = (n0 + crow) < N;    // B row validity (A rows always valid)

    int K2eff = K2;
    if (CK) { int km = (m0 + 128) >> 1; K2eff = (km < K2) ? km : K2; }
    const int nk = K2eff >> 3;

    // stage-load: chunk ik -> stage st
    const long long arow = (long long)(m0 + crow) * lda2;
    const long long brow = (long long)(n0 + crow) * ldb2;
    const uint32_t sdst = (uint32_t)(crow * PK + cq) * 4;

#define LOADCHUNK(ik, st)                                                       \
    {                                                                           \
        int k20 = (ik) * 8 + cq;                                                \
        cp16(sA0 + (uint32_t)((st) * 2 + 0) * (128 * PK * 4) + sdst, Ah + arow + k20, true);  \
        cp16(sA0 + (uint32_t)((st) * 2 + 1) * (128 * PK * 4) + sdst, Al + arow + k20, true);  \
        cp16(sB0 + (uint32_t)((st) * 2 + 0) * (128 * PK * 4) + sdst, Bh + brow + k20, bval);  \
        cp16(sB0 + (uint32_t)((st) * 2 + 1) * (128 * PK * 4) + sdst, Bl + brow + k20, bval);  \
        cp_commit();                                                            \
    }

    const int lane = tid & 31, warp = tid >> 5;
    const int wm = warp >> 2, wn = warp & 3;
    const int gp = lane >> 2, tg = lane & 3;

    float acc[4][4][4];
#pragma unroll
    for (int i = 0; i < 4; i++)
#pragma unroll
        for (int j = 0; j < 4; j++)
#pragma unroll
            for (int r = 0; r < 4; r++) acc[i][j][r] = 0.f;

    LOADCHUNK(0, 0);

    for (int ik = 0; ik < nk; ik++) {
        const int cur = ik & 1;
        if (ik + 1 < nk) {
            LOADCHUNK(ik + 1, (ik + 1) & 1);
            cp_wait<1>();
        } else {
            cp_wait<0>();
        }
        __syncthreads();

        const uint32_t* Ahs = sA[cur][0];
        const uint32_t* Als = sA[cur][1];
        const uint32_t* Bhs = sB[cur][0];
        const uint32_t* Bls = sB[cur][1];

        uint32_t bhf[4][2], blf[4][2];
#pragma unroll
        for (int nf = 0; nf < 4; nf++) {
            int nb = (wn << 5) + (nf << 3) + gp;
            int i0 = nb * PK + tg;
            bhf[nf][0] = Bhs[i0];  bhf[nf][1] = Bhs[i0 + 4];
            blf[nf][0] = Bls[i0];  blf[nf][1] = Bls[i0 + 4];
        }
#pragma unroll
        for (int mf = 0; mf < 4; mf++) {
            int mb = (wm << 6) + (mf << 4) + gp;
            int j0 = mb * PK + tg;
            int j1 = j0 + 8 * PK;
            uint32_t ahf[4] = { Ahs[j0], Ahs[j1], Ahs[j0 + 4], Ahs[j1 + 4] };
            uint32_t alf[4] = { Als[j0], Als[j1], Als[j0 + 4], Als[j1 + 4] };
#pragma unroll
            for (int nf = 0; nf < 4; nf++) {
                mma16(acc[mf][nf], ahf, bhf[nf]);
                mma16(acc[mf][nf], ahf, blf[nf]);
                mma16(acc[mf][nf], alf, bhf[nf]);
            }
        }
        __syncthreads();
    }
#undef LOADCHUNK

    // ---- store
#pragma unroll
    for (int mf = 0; mf < 4; mf++) {
#pragma unroll
        for (int nf = 0; nf < 4; nf++) {
            int n = n0 + (wn << 5) + (nf << 3) + 2 * tg;
#pragma unroll
            for (int h = 0; h < 2; h++) {
                int m = m0 + (wm << 6) + (mf << 4) + gp + h * 8;
                float2 v = make_float2(acc[mf][nf][2 * h], acc[mf][nf][2 * h + 1]);
                if (OUT == 2) {
                    if (n < N) {
                        uint32_t hu, lu;
                        split2(v.x, v.y, hu, lu);
                        long long idx = coff + (long long)m * ldc + (n >> 1);
                        Ch[idx] = hu; Cl[idx] = lu;
                    }
                } else {
                    if (OUT == 1) {
                        v.x = v.x * SCALEV + ((n + 0 > m) ? NEGV : 0.f);
                        v.y = v.y * SCALEV + ((n + 1 > m) ? NEGV : 0.f);
                    }
                    if (n < N)
                        *reinterpret_cast<float2*>(Cf + coff + (long long)m * ldc + n) = v;
                }
            }
        }
    }
}

// ---------------- pre-pass: split along last dim ----------------
// out[z][r][c2] = split(in[z*ibs + r*irs + 2*c2 .. +1])
__global__ void splitk(const float* __restrict__ in, uint32_t* __restrict__ oh,
                       uint32_t* __restrict__ ol,
                       int rpb, int c2len, long long irs, long long ibs, long long obs)
{
    long long idx = (long long)blockIdx.x * 256 + threadIdx.x;
    long long total = (long long)rpb * c2len;
    if (idx >= total) return;
    int zb = blockIdx.y;
    int r = (int)(idx / c2len);
    int c2 = (int)(idx - (long long)r * c2len);
    const float* p = in + (long long)zb * ibs + (long long)r * irs + 2 * c2;
    uint32_t h, l;
    split2(p[0], p[1], h, l);
    oh[(long long)zb * obs + idx] = h;
    ol[(long long)zb * obs + idx] = l;
}

// ---------------- pre-pass: transpose + split ----------------
// in [R][C] (row stride irs) -> out planes [C][R/2], pairs along R
__global__ void tsplit(const float* __restrict__ in, uint32_t* __restrict__ oh,
                       uint32_t* __restrict__ ol,
                       int R, int C, long long irs, long long ibs, long long obs)
{
    __shared__ float s[64][33];
    const int zb = blockIdx.z;
    const int r0 = blockIdx.y * 64, c0 = blockIdx.x * 32;
    const float* base = in + (long long)zb * ibs;
    const int t = threadIdx.x;
#pragma unroll
    for (int i = 0; i < 8; i++) {
        int idx = t + 256 * i;
        int lr = idx >> 5, lc = idx & 31;
        int gr = r0 + lr, gc = c0 + lc;
        s[lr][lc] = (gr < R && gc < C) ? base[(long long)gr * irs + gc] : 0.f;
    }
    __syncthreads();
    const int R2 = R >> 1;
#pragma unroll
    for (int i = 0; i < 4; i++) {
        int idx = t + 256 * i;
        int oc = idx >> 5, or2 = idx & 31;
        int c = c0 + oc, r2 = (r0 >> 1) + or2;
        if (c < C && r2 < R2) {
            uint32_t h, l;
            split2(s[2 * or2][oc], s[2 * or2 + 1][oc], h, l);
            long long o = (long long)zb * obs + (long long)c * R2 + r2;
            oh[o] = h; ol[o] = l;
        }
    }
}

// ---------------- rmsnorm -> split planes ----------------
__global__ void rmsnorm_split(const float* __restrict__ x, const float* __restrict__ w,
                              uint32_t* __restrict__ oh, uint32_t* __restrict__ ol)
{
    const float* row = x + (long long)blockIdx.x * QL;
    const int tid = threadIdx.x;
    float ss = 0.f;
#pragma unroll
    for (int j = 0; j < 3; j++) {
        float2 v = *reinterpret_cast<const float2*>(row + 2 * (tid + 256 * j));
        ss += v.x * v.x + v.y * v.y;
    }
    __shared__ float red[8];
    __shared__ float sc_s;
#pragma unroll
    for (int o = 16; o; o >>= 1) ss += __shfl_xor_sync(0xffffffffu, ss, o);
    if ((tid & 31) == 0) red[tid >> 5] = ss;
    __syncthreads();
    if (tid == 0) {
        float tt = 0.f;
#pragma unroll
        for (int i = 0; i < 8; i++) tt += red[i];
        sc_s = rsqrtf(tt / (float)QL + EPSV);
    }
    __syncthreads();
    float sc = sc_s;
#pragma unroll
    for (int j = 0; j < 3; j++) {
        int c2 = tid + 256 * j;
        float2 v = *reinterpret_cast<const float2*>(row + 2 * c2);
        float a = v.x * sc * w[2 * c2];
        float b = v.y * sc * w[2 * c2 + 1];
        uint32_t h, l;
        split2(a, b, h, l);
        long long o = (long long)blockIdx.x * 768 + c2;
        oh[o] = h; ol[o] = l;
    }
}

// ---- kv post: rmsnorm(c_kv)*w + rope(k_pe) -> planes [bs][288] + fp32 copy
__global__ void kvpost_k(const float* __restrict__ kv, const float* __restrict__ w,
                         const float* __restrict__ fc,
                         uint32_t* __restrict__ oh, uint32_t* __restrict__ ol,
                         float* __restrict__ of)
{
    const int bs = blockIdx.x;
    const float* row = kv + (long long)bs * CAT;
    const int tid = threadIdx.x;
    float ss = 0.f;
    {
        float2 v = *reinterpret_cast<const float2*>(row + 2 * tid);
        ss += v.x * v.x + v.y * v.y;
    }
    __shared__ float red[8];
    __shared__ float sc_s;
#pragma unroll
    for (int oo = 16; oo; oo >>= 1) ss += __shfl_xor_sync(0xffffffffu, ss, oo);
    if ((tid & 31) == 0) red[tid >> 5] = ss;
    __syncthreads();
    if (tid == 0) {
        float tt = 0.f;
#pragma unroll
        for (int i = 0; i < 8; i++) tt += red[i];
        sc_s = rsqrtf(tt / (float)KVL + EPSV);
    }
    __syncthreads();
    float sc = sc_s;
    {
        int c2 = tid;   // 0..255
        float2 v = *reinterpret_cast<const float2*>(row + 2 * c2);
        float a = v.x * sc * w[2 * c2];
        float b = v.y * sc * w[2 * c2 + 1];
        uint32_t h, l;
        split2(a, b, h, l);
        long long o = (long long)bs * CAT2 + c2;
        oh[o] = h; ol[o] = l;
        *reinterpret_cast<float2*>(of + (long long)bs * CAT + 2 * c2) = make_float2(a, b);
    }
    if (tid < 32) {
        int s = bs & (SS - 1);
        float e  = row[KVL + 2 * tid];
        float od = row[KVL + 2 * tid + 1];
        float c  = fc[s * ROPE + 2 * tid];
        float sn = fc[s * ROPE + 2 * tid + 1];
        float re = e * c - od * sn;
        float ro = e * sn + od * c;
        uint32_t h, l;
        split2(re, ro, h, l);
        long long o = (long long)bs * CAT2 + 256 + tid;
        oh[o] = h; ol[o] = l;
        *reinterpret_cast<float2*>(of + (long long)bs * CAT + KVL + 2 * tid) = make_float2(re, ro);
    }
}

// ---- rope on q_pe (from q planes) -> qcat planes pe section ----
__global__ void ropeq_k(const uint32_t* __restrict__ qh, const uint32_t* __restrict__ qlp,
                        const float* __restrict__ fc,
                        uint32_t* __restrict__ oh, uint32_t* __restrict__ ol)
{
    const int bs = blockIdx.x;
    const int s = bs & (SS - 1);
    for (int t = threadIdx.x; t < HH * 32; t += 256) {
        int h = t >> 5, i = t & 31;
        long long src = (long long)bs * QD2 + h * 96 + 64 + i;
        float e, o;
        unsplit(qh[src], qlp[src], e, o);
        float c  = fc[s * ROPE + 2 * i];
        float sn = fc[s * ROPE + 2 * i + 1];
        float re = e * c - o * sn;
        float ro = e * sn + o * c;
        uint32_t hu, lu;
        split2(re, ro, hu, lu);
        long long dst = (long long)bs * (HH * CAT2) + h * CAT2 + 256 + i;
        oh[dst] = hu; ol[dst] = lu;
    }
}

// ---- softmax over rows of 1024 -> P planes [row][512] ----
__global__ void softmax_k(const float* __restrict__ S,
                          uint32_t* __restrict__ ph, uint32_t* __restrict__ pl)
{
    const float* row = S + (long long)blockIdx.x * 1024;
    const int tid = threadIdx.x;
    float4 v = *reinterpret_cast<const float4*>(row + 4 * tid);
    float mx = fmaxf(fmaxf(v.x, v.y), fmaxf(v.z, v.w));
    __shared__ float red[8];
    __shared__ float bval;
#pragma unroll
    for (int o = 16; o; o >>= 1) mx = fmaxf(mx, __shfl_xor_sync(0xffffffffu, mx, o));
    if ((tid & 31) == 0) red[tid >> 5] = mx;
    __syncthreads();
    if (tid == 0) {
        float tt = red[0];
#pragma unroll
        for (int i = 1; i < 8; i++) tt = fmaxf(tt, red[i]);
        bval = tt;
    }
    __syncthreads();
    mx = bval;
    v.x = __expf(v.x - mx); v.y = __expf(v.y - mx);
    v.z = __expf(v.z - mx); v.w = __expf(v.w - mx);
    float sum = v.x + v.y + v.z + v.w;
    __syncthreads();
#pragma unroll
    for (int o = 16; o; o >>= 1) sum += __shfl_xor_sync(0xffffffffu, sum, o);
    if ((tid & 31) == 0) red[tid >> 5] = sum;
    __syncthreads();
    if (tid == 0) {
        float tt = 0.f;
#pragma unroll
        for (int i = 0; i < 8; i++) tt += red[i];
        bval = 1.f / tt;
    }
    __syncthreads();
    float inv = bval;
    long long o = (long long)blockIdx.x * 512 + 2 * tid;
    uint32_t h0, l0, h1, l1;
    split2(v.x * inv, v.y * inv, h0, l0);
    split2(v.z * inv, v.w * inv, h1, l1);
    ph[o] = h0; pl[o] = l0;
    ph[o + 1] = h1; pl[o + 1] = l1;
}

// ---------------- host ----------------
extern "C" void kernel_launch(void* const* d_in, const int* in_sizes, int n_in,
                              void* d_out, int out_size)
{
    (void)in_sizes; (void)n_in; (void)out_size;
    const float* x      = (const float*)d_in[0];
    const float* fc     = (const float*)d_in[1];
    /* mask d_in[2] handled analytically (start_pos == 0, causal) */
    const float* wq_a   = (const float*)d_in[3];
    const float* qnw    = (const float*)d_in[4];
    const float* wq_b   = (const float*)d_in[5];
    const float* wkv_a  = (const float*)d_in[6];
    const float* kvnw   = (const float*)d_in[7];
    const float* wkv_b  = (const float*)d_in[8];
    const float* wo     = (const float*)d_in[9];
    float* out = (float*)d_out;

#define GSYM(p, s) cudaGetSymbolAddress((void**)&p, s)
    float *qlora_f, *kv_f, *kvcat_f, *scores;
    GSYM(qlora_f, g_qlora_f); GSYM(kv_f, g_kv_f);
    GSYM(kvcat_f, g_kvcat_f); GSYM(scores, g_scores);
    uint32_t *xh,*xl,*wqaTh,*wqaTl,*wkvaTh,*wkvaTl,*wqbTh,*wqbTl;
    uint32_t *wkvb1Th,*wkvb1Tl,*wkvb2h,*wkvb2l,*woTh,*woTl;
    uint32_t *qlh,*qll,*kvch,*kvcl,*kvTh,*kvTl,*qh,*qlp,*qch,*qcl;
    uint32_t *Ph,*Pl,*ath,*atl,*prh,*prl;
    GSYM(xh,g_xh); GSYM(xl,g_xl);
    GSYM(wqaTh,g_wqaT_h); GSYM(wqaTl,g_wqaT_l);
    GSYM(wkvaTh,g_wkvaT_h); GSYM(wkvaTl,g_wkvaT_l);
    GSYM(wqbTh,g_wqbT_h); GSYM(wqbTl,g_wqbT_l);
    GSYM(wkvb1Th,g_wkvb1T_h); GSYM(wkvb1Tl,g_wkvb1T_l);
    GSYM(wkvb2h,g_wkvb2_h); GSYM(wkvb2l,g_wkvb2_l);
    GSYM(woTh,g_woT_h); GSYM(woTl,g_woT_l);
    GSYM(qlh,g_ql_h); GSYM(qll,g_ql_l);
    GSYM(kvch,g_kvc_h); GSYM(kvcl,g_kvc_l);
    GSYM(kvTh,g_kvT_h); GSYM(kvTl,g_kvT_l);
    GSYM(qh,g_q_h); GSYM(qlp,g_q_l);
    GSYM(qch,g_qcat_h); GSYM(qcl,g_qcat_l);
    GSYM(Ph,g_P_h); GSYM(Pl,g_P_l);
    GSYM(ath,g_attn_h); GSYM(atl,g_attn_l);
    GSYM(prh,g_proj_h); GSYM(prl,g_proj_l);
#undef GSYM

    // ---- pre-pass: split / transpose-split static operands
    splitk<<<dim3((BS*2048 + 255)/256, 1), 256>>>(x, xh, xl, BS, 2048, DIM, 0, 0);
    tsplit<<<dim3(48, 64, 1), 256>>>(wq_a, wqaTh, wqaTl, DIM, QL, QL, 0, 0);
    tsplit<<<dim3(18, 64, 1), 256>>>(wkv_a, wkvaTh, wkvaTl, DIM, CAT, CAT, 0, 0);
    tsplit<<<dim3(192, 24, 1), 256>>>(wq_b, wqbTh, wqbTl, QL, QD, QD, 0, 0);
    tsplit<<<dim3(16, 2, 32), 256>>>(wkv_b, wkvb1Th, wkvb1Tl, NOPE, KVL, KVL,
                                     (long long)256*KVL, (long long)KVL*64);
    splitk<<<dim3((128*256 + 255)/256, 32), 256>>>(wkv_b + (long long)NOPE*KVL,
                                     wkvb2h, wkvb2l, VD, 256, KVL,
                                     (long long)256*KVL, (long long)VD*256);
    tsplit<<<dim3(128, 64, 1), 256>>>(wo, woTh, woTl, DIM, DIM, DIM, 0, 0);

    // 1. qlora_f = x @ wq_a^T-planes        [2048,1536]
    gemm2<0,false><<<dim3(12,16,1), 256>>>(xh, xl, wqaTh, wqaTl,
        qlora_f, nullptr, nullptr, BS, QL, 2048, 2048, 2048, QL,
        0,0, 0,0, 0,0, 1);
    // 2. kv_f = x @ wkv_a                   [2048,576]
    gemm2<0,false><<<dim3(5,16,1), 256>>>(xh, xl, wkvaTh, wkvaTl,
        kv_f, nullptr, nullptr, BS, CAT, 2048, 2048, 2048, CAT,
        0,0, 0,0, 0,0, 1);
    // 3. rmsnorm(qlora) -> planes
    rmsnorm_split<<<BS, 256>>>(qlora_f, qnw, qlh, qll);
    // 4. kvpost -> kvcat planes + fp32; then kvT transpose-split (c_kv only)
    kvpost_k<<<BS, 256>>>(kv_f, kvnw, fc, kvch, kvcl, kvcat_f);
    tsplit<<<dim3(16, 16, 2), 256>>>(kvcat_f, kvTh, kvTl, SS, KVL, CAT,
                                     (long long)SS*CAT, (long long)KVL*512);
    // 5. q planes = qlora planes @ wq_b     [2048,6144] split store
    gemm2<2,false><<<dim3(48,16,1), 256>>>(qlh, qll, wqbTh, wqbTl,
        nullptr, qh, qlp, BS, QD, 768, 768, 768, QD2,
        0,0, 0,0, 0,0, 1);
    // 6. rope(q_pe) -> qcat pe section
    ropeq_k<<<BS, 256>>>(qh, qlp, fc, qch, qcl);
    // 7. qcat nope = q_nope @ wkv_b[h,:128]^T-planes (per head), split store
    gemm2<2,false><<<dim3(4,16,HH), 256>>>(qh, qlp, wkvb1Th, wkvb1Tl,
        nullptr, qch, qcl, BS, KVL, 64, QD2, 64, HH*CAT2,
        0, 96, 0, (long long)KVL*64, 0, CAT2, HH);
    // 8. scores = qcat ⊗ kvcat (+scale+mask), fp32
    gemm2<1,false><<<dim3(8,8,BB*HH), 256>>>(qch, qcl, kvch, kvcl,
        scores, nullptr, nullptr, SS, SS, CAT2, HH*CAT2, CAT2, SS,
        (long long)SS*HH*CAT2, CAT2,
        (long long)SS*CAT2, 0,
        (long long)HH*SS*SS, (long long)SS*SS, HH);
    // 9. softmax -> P planes
    softmax_k<<<BB*HH*SS, 256>>>(scores, Ph, Pl);
    // 10. attn planes = P ⊗ kvT (causal K bound), split store
    gemm2<2,true><<<dim3(4,8,BB*HH), 256>>>(Ph, Pl, kvTh, kvTl,
        nullptr, ath, atl, SS, KVL, 512, 512, 512, HH*256,
        (long long)HH*SS*512, (long long)SS*512,
        (long long)KVL*512, 0,
        (long long)SS*HH*256, 256, HH);
    // 11. proj planes = attn ⊗ wkv_b[h,128:,:] (per head), split store
    gemm2<2,false><<<dim3(1,16,HH), 256>>>(ath, atl, wkvb2h, wkvb2l,
        nullptr, prh, prl, BS, VD, 256, HH*256, 256, 2048,
        0, 256, 0, (long long)VD*256, 0, 64, HH);
    // 12. out = proj ⊗ wo                   [2048,4096] fp32
    gemm2<0,false><<<dim3(32,16,1), 256>>>(prh, prl, woTh, woTl,
        out, nullptr, nullptr, BS, DIM, 2048, 2048, 2048, DIM,
        0,0, 0,0, 0,0, 1);
}